// round 13
// baseline (speedup 1.0000x reference)
#include <cuda_runtime.h>
#include <cuda_bf16.h>
#include <cuda_fp16.h>
#include <math.h>
#include <stdint.h>

#define HIDDEN 3584
#define NQ 28
#define NKV 4
#define HD 128
#define SEQ 2048
#define BATCH 2
#define NREP (NQ / NKV)
#define QSCALE 0.08838834764831845f   // 1/sqrt(128)
#define CW 4608                       // fused QKV output width (3584+512+512)

// ---------------- scratch (static device arrays; no cudaMalloc) -------------
__device__ float  g_tmp[BATCH * SEQ * CW];             // fused proj out (fp32)
__device__ __half g_a[BATCH * SEQ * HIDDEN];           // X quant, later ctx
__device__ __half g_wqkv[CW * HIDDEN];                 // wq|wk|wv rows
__device__ float  g_bqkv[CW];                          // bq|bk|bv
__device__ __half g_wo[HIDDEN * HIDDEN];
__device__ __half g_q[BATCH * NQ * SEQ * HD];          // Q [B,Hq,S,D] (pre-scaled)
__device__ __half g_k[BATCH * NKV * SEQ * HD];         // K [B,Hkv,S,D]
__device__ __half g_v[BATCH * NKV * HD * SEQ];         // V [B,Hkv,D,S] (transposed)
__device__ float  g_cs[SEQ * 64];                      // RoPE cos table
__device__ float  g_sn[SEQ * 64];                      // RoPE sin table
__device__ int    g_mask_nz;                           // mask-nonzero flag

// ---------------- robust position decode (int64 / int32 / float32) ----------
__device__ __forceinline__ float get_pos(const void* pos, int s)
{
    const int* p32 = (const int*)pos;
    if (p32[2] == 1 && p32[3] == 0) {
        return (float)((const long long*)pos)[s];
    } else if (p32[1] == 1 && p32[2] == 2) {
        return (float)p32[s];
    } else {
        return ((const float*)pos)[s];
    }
}

// ---------------- fused prep: weight/X quant + bias concat + rope table ------
__device__ __forceinline__ void q4(const float* src, __half* dst, int j)
{
    float4 v = ((const float4*)src)[j];
    __half2* op = (__half2*)(dst + 4 * (size_t)j);
    op[0] = __floats2half2_rn(v.x, v.y);
    op[1] = __floats2half2_rn(v.z, v.w);
}

__global__ void prep_kernel(const float* wq, const float* wk,
                            const float* wv, const float* wo, const float* X,
                            const float* bq, const float* bk, const float* bv,
                            const void* pos,
                            __half* wqkv, __half* pwo, __half* xa, float* bqkv,
                            int nq4, int nk4, int no4, int nx4)
{
    int i = blockIdx.x * blockDim.x + threadIdx.x;
    if (i == 0) g_mask_nz = 0;
    int j = i;
    if (j < nq4) { q4(wq, wqkv, j); return; }
    j -= nq4;
    if (j < nk4) { q4(wk, wqkv + (size_t)nq4 * 4, j); return; }
    j -= nk4;
    if (j < nk4) { q4(wv, wqkv + (size_t)(nq4 + nk4) * 4, j); return; }
    j -= nk4;
    if (j < no4) { q4(wo, pwo, j); return; }
    j -= no4;
    if (j < nx4) { q4(X, xa, j); return; }
    j -= nx4;
    if (j < CW / 4) {
        int e = j * 4;
#pragma unroll
        for (int u = 0; u < 4; u++) {
            int c = e + u;
            float b;
            if (c < NQ * HD) b = bq[c];
            else if (c < NQ * HD + NKV * HD) b = bk[c - NQ * HD];
            else b = bv[c - NQ * HD - NKV * HD];
            bqkv[c] = b;
        }
        return;
    }
    j -= CW / 4;
    if (j < SEQ * 64) {
        int d = j & 63, s = j >> 6;
        float inv = powf(1000000.0f, -(float)d / 64.0f);
        float ang = get_pos(pos, s) * inv;
        float sn, cs;
        sincosf(ang, &sn, &cs);
        g_cs[j] = cs;
        g_sn[j] = sn;
    }
}

// ---------------- mask zero check --------------------------------------------
__global__ void mask_check(const float4* __restrict__ m, int n4)
{
    int i = blockIdx.x * blockDim.x + threadIdx.x;
    bool nz = false;
    if (i < n4) {
        float4 v = m[i];
        nz = (v.x != 0.f) || (v.y != 0.f) || (v.z != 0.f) || (v.w != 0.f);
    }
    unsigned b = __ballot_sync(0xffffffffu, nz);
    if (b && (threadIdx.x & 31) == 0) atomicOr(&g_mask_nz, 1);
}

// ---------------- mma / cp.async helpers ------------------------------------
__device__ __forceinline__ void ldsm4(uint32_t* r, uint32_t saddr)
{
    asm volatile("ldmatrix.sync.aligned.m8n8.x4.shared.b16 {%0,%1,%2,%3}, [%4];"
                 : "=r"(r[0]), "=r"(r[1]), "=r"(r[2]), "=r"(r[3]) : "r"(saddr));
}
__device__ __forceinline__ void mma_fp16(float* c, const uint32_t* a,
                                         uint32_t b0, uint32_t b1)
{
    asm volatile(
        "mma.sync.aligned.m16n8k16.row.col.f32.f16.f16.f32 "
        "{%0,%1,%2,%3}, {%4,%5,%6,%7}, {%8,%9}, {%0,%1,%2,%3};"
        : "+f"(c[0]), "+f"(c[1]), "+f"(c[2]), "+f"(c[3])
        : "r"(a[0]), "r"(a[1]), "r"(a[2]), "r"(a[3]), "r"(b0), "r"(b1));
}
__device__ __forceinline__ void cp16(uint32_t dst, const void* src)
{
    asm volatile("cp.async.ca.shared.global [%0], [%1], 16;" :: "r"(dst), "l"(src));
}
#define CP_COMMIT() asm volatile("cp.async.commit_group;")
#define CP_WAIT0()  asm volatile("cp.async.wait_group 0;")
#define CP_WAIT1()  asm volatile("cp.async.wait_group 1;")
#define CP_WAIT2()  asm volatile("cp.async.wait_group 2;")

__device__ __forceinline__ float qmax4(float v)
{
    v = fmaxf(v, __shfl_xor_sync(0xffffffffu, v, 1));
    v = fmaxf(v, __shfl_xor_sync(0xffffffffu, v, 2));
    return v;
}
__device__ __forceinline__ float qsum4(float v)
{
    v += __shfl_xor_sync(0xffffffffu, v, 1);
    v += __shfl_xor_sync(0xffffffffu, v, 2);
    return v;
}

// ---------------- fp16 tensor GEMM: C = A*W^T (+bias) ------------------------
// CTA 128x256, 8 warps (64x64 each), k-chunk 64, 4-stage cp.async ring
// (one barrier per chunk). A: [M,K], W: [N,K]. M%128==0, N%256==0, K%64==0.
#define SB 72                                  // smem row stride (elems)
#define GA_B (128 * SB * 2)                    // 18432 B (A tile)
#define GW_B (256 * SB * 2)                    // 36864 B (W tile)
#define GSTAGE_B (GA_B + GW_B)                 // 55296 B per stage
#define GSM_TOTAL (4 * GSTAGE_B)               // 221184 B

__global__ __launch_bounds__(256) void gemm_fp16(
    const __half* __restrict__ A, const __half* __restrict__ W,
    const float* __restrict__ bias, float* __restrict__ C,
    int M, int N, int K)
{
    extern __shared__ __align__(16) char gsm[];
    const uint32_t smb = (uint32_t)__cvta_generic_to_shared(gsm);

    const int t    = threadIdx.x;
    const int lane = t & 31;
    const int w    = t >> 5;
    const int wm   = (w >> 2) * 64;    // 0 / 64
    const int wn   = (w & 3) * 64;     // 0..192
    const int m0   = blockIdx.y * 128;
    const int n0   = blockIdx.x * 256;
    const int NC   = K / 64;

    float acc[4][8][4];
#pragma unroll
    for (int i = 0; i < 4; i++)
#pragma unroll
        for (int j = 0; j < 8; j++)
#pragma unroll
            for (int e = 0; e < 4; e++) acc[i][j][e] = 0.f;

    auto issue = [&](int chunk, int st) {
        const int kk = chunk * 64;
        uint32_t dA = smb + st * GSTAGE_B;
        uint32_t dW = dA + GA_B;
#pragma unroll
        for (int i = 0; i < 4; i++) {           // A: 1024 16B chunks
            int idx = t + 256 * i;
            int row = idx >> 3;
            int c8  = (idx & 7) * 8;
            cp16(dA + (row * SB + c8) * 2, A + (size_t)(m0 + row) * K + kk + c8);
        }
#pragma unroll
        for (int i = 0; i < 8; i++) {           // W: 2048 16B chunks
            int idx = t + 256 * i;
            int row = idx >> 3;
            int c8  = (idx & 7) * 8;
            cp16(dW + (row * SB + c8) * 2, W + (size_t)(n0 + row) * K + kk + c8);
        }
        CP_COMMIT();
    };

    issue(0, 0);
    issue(1, 1);
    issue(2, 2);

    for (int p = 0; p < NC; p++) {
        const int rem = NC - 1 - p;
        if (rem >= 2) { CP_WAIT2(); } else if (rem == 1) { CP_WAIT1(); } else { CP_WAIT0(); }
        __syncthreads();
        // stage (p+3)%4 == (p-1)%4: consumed last iteration, barrier passed.
        if (p + 3 < NC) issue(p + 3, (p + 3) & 3);

        const uint32_t bA = smb + (p & 3) * GSTAGE_B;
        const uint32_t bW = bA + GA_B;
        const int arow = lane & 15;
        const int ahalf = (lane >> 4) * 8;
#pragma unroll
        for (int kk = 0; kk < 64; kk += 16) {
            const int acol = kk + ahalf;
            uint32_t a[4][4];
#pragma unroll
            for (int mi = 0; mi < 4; mi++)
                ldsm4(a[mi], bA + ((wm + mi * 16 + arow) * SB + acol) * 2);
#pragma unroll
            for (int ni = 0; ni < 4; ni++) {
                uint32_t bfr[4];
                ldsm4(bfr, bW + ((wn + ni * 16 + arow) * SB + acol) * 2);
#pragma unroll
                for (int mi = 0; mi < 4; mi++)
#pragma unroll
                    for (int hh = 0; hh < 2; hh++)
                        mma_fp16(acc[mi][ni * 2 + hh], a[mi],
                                 bfr[hh], bfr[2 + hh]);
            }
        }
    }

    // epilogue: warp writes 64x64
#pragma unroll
    for (int mi = 0; mi < 4; mi++) {
        int row0 = m0 + wm + mi * 16 + (lane >> 2);
#pragma unroll
        for (int nj = 0; nj < 8; nj++) {
            int col0 = n0 + wn + nj * 8 + (lane & 3) * 2;
            float b0 = bias ? __ldg(&bias[col0]) : 0.f;
            float b1 = bias ? __ldg(&bias[col0 + 1]) : 0.f;
            float* c = acc[mi][nj];
            *(float2*)&C[(size_t)row0 * N + col0] =
                make_float2(c[0] + b0, c[1] + b1);
            *(float2*)&C[(size_t)(row0 + 8) * N + col0] =
                make_float2(c[2] + b0, c[3] + b1);
        }
    }
}

// ---- post-proj: RoPE Q+K and V transpose from fused [B,S,CW] output --------
#define TOTQK (BATCH * (NQ + NKV) * SEQ * 64)
#define TOTV  (BATCH * NKV * HD * SEQ)

__global__ void postproj_kernel(const float* __restrict__ in,
                                __half* __restrict__ oq, __half* __restrict__ ok,
                                __half* __restrict__ ov)
{
    int idx = blockIdx.x * blockDim.x + threadIdx.x;
    if (idx < TOTQK) {
        int per = idx;
        int d = per & 63;      per >>= 6;
        int s = per & (SEQ - 1); per >>= 11;
        int h = per & 31;
        int b = per >> 5;

        size_t ibase = ((size_t)b * SEQ + s) * CW + h * HD;
        float x1 = in[ibase + d];
        float x2 = in[ibase + d + 64];

        float cs = g_cs[(s << 6) + d];
        float sn = g_sn[(s << 6) + d];
        float v0 = x1 * cs - x2 * sn;
        float v1 = x2 * cs + x1 * sn;

        if (h < NQ) {
            size_t obase = (((size_t)b * NQ + h) * SEQ + s) * HD;
            oq[obase + d]      = __float2half(v0 * QSCALE);
            oq[obase + d + 64] = __float2half(v1 * QSCALE);
        } else {
            size_t obase = (((size_t)b * NKV + (h - NQ)) * SEQ + s) * HD;
            ok[obase + d]      = __float2half(v0);
            ok[obase + d + 64] = __float2half(v1);
        }
        return;
    }
    int j = idx - TOTQK;
    if (j < TOTV) {
        int per = j;
        int s = per & (SEQ - 1); per >>= 11;
        int d = per & (HD - 1);  per >>= 7;
        int h = per % NKV;
        int b = per / NKV;
        ov[j] = __float2half(in[((size_t)b * SEQ + s) * CW + (NQ + NKV) * HD + h * HD + d]);
    }
}

// ---------------- mma flash attention (fp16, 2-stage K/V) --------------------
#define AQW 64
#define KTS 64
#define KSTR 136
#define VSTR 72
#define ASTAGE_B (KTS * KSTR * 2 + HD * VSTR * 2)   // 35840 per stage
#define ASM_TOTAL (2 * ASTAGE_B)                    // 71680

__global__ __launch_bounds__(128) void attn_mma(
    const __half* __restrict__ Qg, const __half* __restrict__ Kg,
    const __half* __restrict__ Vg, const float* __restrict__ maskg,
    __half* __restrict__ Out)
{
    extern __shared__ __align__(16) char smraw[];
    const uint32_t smb = (uint32_t)__cvta_generic_to_shared(smraw);

    const int t    = threadIdx.x;
    const int lane = t & 31;
    const int w    = t >> 5;
    const int q0   = blockIdx.x * AQW;
    const int h    = blockIdx.y;
    const int b    = blockIdx.z;
    const int hkv  = h / NREP;
    const int wm   = w * 16;
    const int mnz  = g_mask_nz;

    const __half* q_b = Qg + (((size_t)(b * NQ + h) * SEQ) + q0) * HD;
    const __half* k_b = Kg + (size_t)(b * NKV + hkv) * SEQ * HD;
    const __half* v_b = Vg + (size_t)(b * NKV + hkv) * HD * SEQ;
    const float*  m_b = maskg + ((size_t)b * SEQ + q0) * SEQ;

    for (int c = t; c < 1024; c += 128) {
        int row = c >> 4, off = (c & 15) * 8;
        cp16(smb + (row * KSTR + off) * 2, q_b + (size_t)row * HD + off);
    }
    CP_COMMIT(); CP_WAIT0();
    __syncthreads();

    uint32_t qf[8][4];
    {
        const int arow = lane & 15;
#pragma unroll
        for (int ks = 0; ks < 8; ks++) {
            int acol = ks * 16 + (lane >> 4) * 8;
            ldsm4(qf[ks], smb + ((wm + arow) * KSTR + acol) * 2);
        }
    }
    __syncthreads();

    auto loadKV = [&](int kt, int buf) {
        int k0 = kt * KTS;
        uint32_t smk = smb + buf * ASTAGE_B;
        uint32_t smv = smk + KTS * KSTR * 2;
        for (int c = t; c < 1024; c += 128) {
            int row = c >> 4, off = (c & 15) * 8;
            cp16(smk + (row * KSTR + off) * 2, k_b + (size_t)(k0 + row) * HD + off);
        }
        for (int c = t; c < 1024; c += 128) {
            int row = c >> 3, off = (c & 7) * 8;
            cp16(smv + (row * VSTR + off) * 2, v_b + (size_t)row * SEQ + k0 + off);
        }
        CP_COMMIT();
    };

    float O[16][4];
#pragma unroll
    for (int j = 0; j < 16; j++)
#pragma unroll
        for (int e = 0; e < 4; e++) O[j][e] = 0.f;
    float mrow0 = -1e30f, mrow1 = -1e30f;
    float lrow0 = 0.f, lrow1 = 0.f;

    const int r0q = wm + (lane >> 2);
    const int cq  = (lane & 3) * 2;
    const float* mrow_a = m_b + (size_t)r0q * SEQ;
    const float* mrow_b = m_b + (size_t)(r0q + 8) * SEQ;

    loadKV(0, 0);

    const int NT = SEQ / KTS;
    for (int kt = 0; kt < NT; kt++) {
        const int cur = kt & 1;
        CP_WAIT0();
        __syncthreads();
        if (kt + 1 < NT) loadKV(kt + 1, cur ^ 1);

        const uint32_t smk = smb + cur * ASTAGE_B;
        const uint32_t smv = smk + KTS * KSTR * 2;
        const int k0 = kt * KTS;

        float sc[8][4];
#pragma unroll
        for (int j = 0; j < 8; j++)
#pragma unroll
            for (int e = 0; e < 4; e++) sc[j][e] = 0.f;

        const int arow = lane & 15;
#pragma unroll
        for (int ks = 0; ks < 8; ks++) {
            int acol = ks * 16 + (lane >> 4) * 8;
#pragma unroll
            for (int n = 0; n < 4; n++) {
                uint32_t bk[4];
                ldsm4(bk, smk + ((n * 16 + arow) * KSTR + acol) * 2);
#pragma unroll
                for (int hh = 0; hh < 2; hh++)
                    mma_fp16(sc[n * 2 + hh], qf[ks], bk[hh], bk[2 + hh]);
            }
        }

        if (mnz) {
#pragma unroll
            for (int j = 0; j < 8; j++) {
                float2 mk0 = __ldg((const float2*)(mrow_a + k0 + j * 8 + cq));
                float2 mk1 = __ldg((const float2*)(mrow_b + k0 + j * 8 + cq));
                sc[j][0] += mk0.x; sc[j][1] += mk0.y;
                sc[j][2] += mk1.x; sc[j][3] += mk1.y;
            }
        }
        float mx0 = -1e30f, mx1 = -1e30f;
#pragma unroll
        for (int j = 0; j < 8; j++) {
            mx0 = fmaxf(mx0, fmaxf(sc[j][0], sc[j][1]));
            mx1 = fmaxf(mx1, fmaxf(sc[j][2], sc[j][3]));
        }
        mx0 = qmax4(mx0); mx1 = qmax4(mx1);
        float mn0 = fmaxf(mrow0, mx0), mn1 = fmaxf(mrow1, mx1);
        float cr0 = __expf(mrow0 - mn0), cr1 = __expf(mrow1 - mn1);
        mrow0 = mn0; mrow1 = mn1;
        lrow0 *= cr0; lrow1 *= cr1;
#pragma unroll
        for (int j = 0; j < 16; j++) {
            O[j][0] *= cr0; O[j][1] *= cr0;
            O[j][2] *= cr1; O[j][3] *= cr1;
        }

        uint32_t ap[4][4];
#pragma unroll
        for (int j = 0; j < 8; j++) {
            float p0 = __expf(sc[j][0] - mn0);
            float p1 = __expf(sc[j][1] - mn0);
            float p2 = __expf(sc[j][2] - mn1);
            float p3 = __expf(sc[j][3] - mn1);
            lrow0 += p0 + p1; lrow1 += p2 + p3;
            int kk = j >> 1, hi = j & 1;
            __half2 ph01 = __floats2half2_rn(p0, p1);
            __half2 ph23 = __floats2half2_rn(p2, p3);
            ap[kk][hi * 2 + 0] = *(uint32_t*)&ph01;
            ap[kk][hi * 2 + 1] = *(uint32_t*)&ph23;
        }

#pragma unroll
        for (int kk = 0; kk < 4; kk++) {
            int acol = kk * 16 + (lane >> 4) * 8;
#pragma unroll
            for (int n = 0; n < 8; n++) {
                uint32_t bv[4];
                ldsm4(bv, smv + ((n * 16 + arow) * VSTR + acol) * 2);
#pragma unroll
                for (int hh = 0; hh < 2; hh++)
                    mma_fp16(O[n * 2 + hh], ap[kk], bv[hh], bv[2 + hh]);
            }
        }
    }

    float lt0 = qsum4(lrow0), lt1 = qsum4(lrow1);
    float inv0 = 1.f / lt0, inv1 = 1.f / lt1;

    const int r0 = q0 + r0q;
    __half* o_b = Out + ((size_t)b * SEQ) * (NQ * HD) + h * HD;
#pragma unroll
    for (int j = 0; j < 16; j++) {
        int col = j * 8 + cq;
        __half2 v0 = __floats2half2_rn(O[j][0] * inv0, O[j][1] * inv0);
        __half2 v1 = __floats2half2_rn(O[j][2] * inv1, O[j][3] * inv1);
        *(__half2*)&o_b[(size_t)r0 * (NQ * HD) + col]       = v0;
        *(__half2*)&o_b[(size_t)(r0 + 8) * (NQ * HD) + col] = v1;
    }
}

// ---------------- launcher ----------------------------------------------------
extern "C" void kernel_launch(void* const* d_in, const int* in_sizes, int n_in,
                              void* d_out, int out_size)
{
    const float* X    = (const float*)d_in[0];
    const float* mask = (const float*)d_in[1];
    const void*  pos  = (const void*)d_in[2];
    const float* wq   = (const float*)d_in[3];
    const float* bq   = (const float*)d_in[4];
    const float* wk   = (const float*)d_in[5];
    const float* bk   = (const float*)d_in[6];
    const float* wv   = (const float*)d_in[7];
    const float* bv   = (const float*)d_in[8];
    const float* wo   = (const float*)d_in[9];
    float*       out  = (float*)d_out;

    float *tmp, *bqkv;
    __half *a, *pwqkv, *pwo, *q, *k, *v;
    cudaGetSymbolAddress((void**)&tmp,   g_tmp);
    cudaGetSymbolAddress((void**)&a,     g_a);
    cudaGetSymbolAddress((void**)&pwqkv, g_wqkv);
    cudaGetSymbolAddress((void**)&bqkv,  g_bqkv);
    cudaGetSymbolAddress((void**)&pwo,   g_wo);
    cudaGetSymbolAddress((void**)&q,     g_q);
    cudaGetSymbolAddress((void**)&k,     g_k);
    cudaGetSymbolAddress((void**)&v,     g_v);

    cudaFuncSetAttribute(attn_mma, cudaFuncAttributeMaxDynamicSharedMemorySize,
                         ASM_TOTAL);
    cudaFuncSetAttribute(gemm_fp16, cudaFuncAttributeMaxDynamicSharedMemorySize,
                         GSM_TOTAL);

    const int M = BATCH * SEQ;   // 4096

    // prep: all quants + bias concat + rope table + flag clear
    {
        const int nq4 = (NQ * HD * HIDDEN) / 4;
        const int nk4 = (NKV * HD * HIDDEN) / 4;
        const int no4 = (HIDDEN * HIDDEN) / 4;
        const int nx4 = (M * HIDDEN) / 4;
        int total = nq4 + 2 * nk4 + no4 + nx4 + CW / 4 + SEQ * 64;
        prep_kernel<<<(total + 255) / 256, 256>>>(wq, wk, wv, wo, X, bq, bk, bv,
                                                  pos, pwqkv, pwo, a, bqkv,
                                                  nq4, nk4, no4, nx4);
    }
    // mask zero-scan (full scan; sets g_mask_nz)
    {
        int n4 = (BATCH * SEQ * SEQ) / 4;
        mask_check<<<(n4 + 255) / 256, 256>>>((const float4*)mask, n4);
    }
    // fused QKV projection
    {
        dim3 grid(CW / 256, M / 128);
        gemm_fp16<<<grid, 256, GSM_TOTAL>>>(a, pwqkv, bqkv, tmp, M, CW, HIDDEN);
    }
    // RoPE Q+K + V transpose (one launch)
    {
        int total = TOTQK + TOTV;
        postproj_kernel<<<(total + 255) / 256, 256>>>(tmp, q, k, v);
    }
    // attention -> fp16 context written into g_a (X no longer needed)
    {
        dim3 grid(SEQ / AQW, NQ, BATCH);
        attn_mma<<<grid, 128, ASM_TOTAL>>>(q, k, v, mask, a);
    }
    // output projection (no bias)
    {
        dim3 grid(HIDDEN / 256, M / 128);
        gemm_fp16<<<grid, 256, GSM_TOTAL>>>(a, pwo, nullptr, out, M, HIDDEN, HIDDEN);
    }
}

// round 14
// speedup vs baseline: 1.1541x; 1.1541x over previous
#include <cuda_runtime.h>
#include <cuda_bf16.h>
#include <cuda_fp16.h>
#include <math.h>
#include <stdint.h>

#define HIDDEN 3584
#define NQ 28
#define NKV 4
#define HD 128
#define SEQ 2048
#define BATCH 2
#define NREP (NQ / NKV)
#define QSCALE 0.08838834764831845f   // 1/sqrt(128)
#define CW 4608                       // fused QKV output width (3584+512+512)
#define VOFF ((NQ + NKV) * HD)        // V slice offset in fused output

// ---------------- scratch (static device arrays; no cudaMalloc) -------------
__device__ float  g_tmp[BATCH * SEQ * CW];             // fused proj out (fp32)
__device__ __half g_a[BATCH * SEQ * HIDDEN];           // X quant, later ctx
__device__ __half g_wqkv[CW * HIDDEN];                 // wq|wk|wv rows
__device__ float  g_bqkv[CW];                          // bq|bk|bv
__device__ __half g_wo[HIDDEN * HIDDEN];
__device__ __half g_q[BATCH * NQ * SEQ * HD];          // Q [B,Hq,S,D] (pre-scaled)
__device__ __half g_k[BATCH * NKV * SEQ * HD];         // K [B,Hkv,S,D]
__device__ __half g_v[BATCH * NKV * HD * SEQ];         // V [B,Hkv,D,S] (transposed)
__device__ float  g_cs[SEQ * 64];                      // RoPE cos table
__device__ float  g_sn[SEQ * 64];                      // RoPE sin table
__device__ int    g_mask_nz = 0;                       // set-only, idempotent

// ---------------- robust position decode (int64 / int32 / float32) ----------
__device__ __forceinline__ float get_pos(const void* pos, int s)
{
    const int* p32 = (const int*)pos;
    if (p32[2] == 1 && p32[3] == 0) {
        return (float)((const long long*)pos)[s];
    } else if (p32[1] == 1 && p32[2] == 2) {
        return (float)p32[s];
    } else {
        return ((const float*)pos)[s];
    }
}

// ------- fused prep: quants + bias concat + rope table + mask scan ----------
__device__ __forceinline__ void q4(const float* src, __half* dst, int j)
{
    float4 v = ((const float4*)src)[j];
    __half2* op = (__half2*)(dst + 4 * (size_t)j);
    op[0] = __floats2half2_rn(v.x, v.y);
    op[1] = __floats2half2_rn(v.z, v.w);
}

__global__ void prep_kernel(const float* wq, const float* wk,
                            const float* wv, const float* wo, const float* X,
                            const float* bq, const float* bk, const float* bv,
                            const void* pos, const float4* mask,
                            __half* wqkv, __half* pwo, __half* xa, float* bqkv,
                            int nq4, int nk4, int no4, int nx4, int nm4)
{
    int i = blockIdx.x * blockDim.x + threadIdx.x;
    int j = i;
    if (j < nq4) { q4(wq, wqkv, j); return; }
    j -= nq4;
    if (j < nk4) { q4(wk, wqkv + (size_t)nq4 * 4, j); return; }
    j -= nk4;
    if (j < nk4) { q4(wv, wqkv + (size_t)(nq4 + nk4) * 4, j); return; }
    j -= nk4;
    if (j < no4) { q4(wo, pwo, j); return; }
    j -= no4;
    if (j < nx4) { q4(X, xa, j); return; }
    j -= nx4;
    if (j < CW / 4) {
        int e = j * 4;
#pragma unroll
        for (int u = 0; u < 4; u++) {
            int c = e + u;
            float b;
            if (c < NQ * HD) b = bq[c];
            else if (c < NQ * HD + NKV * HD) b = bk[c - NQ * HD];
            else b = bv[c - NQ * HD - NKV * HD];
            bqkv[c] = b;
        }
        return;
    }
    j -= CW / 4;
    if (j < SEQ * 64) {
        int d = j & 63, s = j >> 6;
        float inv = powf(1000000.0f, -(float)d / 64.0f);
        float ang = get_pos(pos, s) * inv;
        float sn, cs;
        sincosf(ang, &sn, &cs);
        g_cs[j] = cs;
        g_sn[j] = sn;
        return;
    }
    j -= SEQ * 64;
    if (j < nm4) {
        float4 v = mask[j];
        bool nz = (v.x != 0.f) || (v.y != 0.f) || (v.z != 0.f) || (v.w != 0.f);
        unsigned b = __ballot_sync(__activemask(), nz);
        if (b && (threadIdx.x & 31) == 0) atomicOr(&g_mask_nz, 1);
    }
}

// ---------------- mma / cp.async helpers ------------------------------------
__device__ __forceinline__ void ldsm4(uint32_t* r, uint32_t saddr)
{
    asm volatile("ldmatrix.sync.aligned.m8n8.x4.shared.b16 {%0,%1,%2,%3}, [%4];"
                 : "=r"(r[0]), "=r"(r[1]), "=r"(r[2]), "=r"(r[3]) : "r"(saddr));
}
__device__ __forceinline__ void mma_fp16(float* c, const uint32_t* a,
                                         uint32_t b0, uint32_t b1)
{
    asm volatile(
        "mma.sync.aligned.m16n8k16.row.col.f32.f16.f16.f32 "
        "{%0,%1,%2,%3}, {%4,%5,%6,%7}, {%8,%9}, {%0,%1,%2,%3};"
        : "+f"(c[0]), "+f"(c[1]), "+f"(c[2]), "+f"(c[3])
        : "r"(a[0]), "r"(a[1]), "r"(a[2]), "r"(a[3]), "r"(b0), "r"(b1));
}
__device__ __forceinline__ void cp16(uint32_t dst, const void* src)
{
    asm volatile("cp.async.ca.shared.global [%0], [%1], 16;" :: "r"(dst), "l"(src));
}
#define CP_COMMIT() asm volatile("cp.async.commit_group;")
#define CP_WAIT0()  asm volatile("cp.async.wait_group 0;")
#define CP_WAIT1()  asm volatile("cp.async.wait_group 1;")
#define CP_WAIT2()  asm volatile("cp.async.wait_group 2;")

__device__ __forceinline__ float qmax4(float v)
{
    v = fmaxf(v, __shfl_xor_sync(0xffffffffu, v, 1));
    v = fmaxf(v, __shfl_xor_sync(0xffffffffu, v, 2));
    return v;
}
__device__ __forceinline__ float qsum4(float v)
{
    v += __shfl_xor_sync(0xffffffffu, v, 1);
    v += __shfl_xor_sync(0xffffffffu, v, 2);
    return v;
}

// ---------------- fp16 tensor GEMM: C = A*W^T (+bias) ------------------------
// CTA 128x256, 8 warps (64x64 each), k-chunk 64, 3-stage cp.async ring.
// (round-12 measured schedule)
#define SB 72                                  // smem row stride (elems)
#define GA_B (128 * SB * 2)                    // 18432 B (A tile)
#define GW_B (256 * SB * 2)                    // 36864 B (W tile)
#define GSTAGE_B (GA_B + GW_B)                 // 55296 B per stage
#define GSM_TOTAL (3 * GSTAGE_B)               // 165888 B

__global__ __launch_bounds__(256) void gemm_fp16(
    const __half* __restrict__ A, const __half* __restrict__ W,
    const float* __restrict__ bias, float* __restrict__ C,
    int M, int N, int K)
{
    extern __shared__ __align__(16) char gsm[];
    const uint32_t smb = (uint32_t)__cvta_generic_to_shared(gsm);

    const int t    = threadIdx.x;
    const int lane = t & 31;
    const int w    = t >> 5;
    const int wm   = (w >> 2) * 64;    // 0 / 64
    const int wn   = (w & 3) * 64;     // 0..192
    const int m0   = blockIdx.y * 128;
    const int n0   = blockIdx.x * 256;
    const int NC   = K / 64;

    float acc[4][8][4];
#pragma unroll
    for (int i = 0; i < 4; i++)
#pragma unroll
        for (int j = 0; j < 8; j++)
#pragma unroll
            for (int e = 0; e < 4; e++) acc[i][j][e] = 0.f;

    auto issue = [&](int chunk, int st) {
        const int kk = chunk * 64;
        uint32_t dA = smb + st * GSTAGE_B;
        uint32_t dW = dA + GA_B;
#pragma unroll
        for (int i = 0; i < 4; i++) {           // A: 1024 16B chunks
            int idx = t + 256 * i;
            int row = idx >> 3;
            int c8  = (idx & 7) * 8;
            cp16(dA + (row * SB + c8) * 2, A + (size_t)(m0 + row) * K + kk + c8);
        }
#pragma unroll
        for (int i = 0; i < 8; i++) {           // W: 2048 16B chunks
            int idx = t + 256 * i;
            int row = idx >> 3;
            int c8  = (idx & 7) * 8;
            cp16(dW + (row * SB + c8) * 2, W + (size_t)(n0 + row) * K + kk + c8);
        }
        CP_COMMIT();
    };

    issue(0, 0);
    if (NC > 1) issue(1, 1);
    if (NC > 2) issue(2, 2);

    for (int p = 0; p < NC; p++) {
        const int rem = NC - 1 - p;
        if (rem >= 2) { CP_WAIT2(); } else if (rem == 1) { CP_WAIT1(); } else { CP_WAIT0(); }
        __syncthreads();

        const int cur = p % 3;
        const uint32_t bA = smb + cur * GSTAGE_B;
        const uint32_t bW = bA + GA_B;
        const int arow = lane & 15;
        const int ahalf = (lane >> 4) * 8;
#pragma unroll
        for (int kk = 0; kk < 64; kk += 16) {
            const int acol = kk + ahalf;
            uint32_t a[4][4];
#pragma unroll
            for (int mi = 0; mi < 4; mi++)
                ldsm4(a[mi], bA + ((wm + mi * 16 + arow) * SB + acol) * 2);
#pragma unroll
            for (int ni = 0; ni < 4; ni++) {
                uint32_t bfr[4];
                ldsm4(bfr, bW + ((wn + ni * 16 + arow) * SB + acol) * 2);
#pragma unroll
                for (int mi = 0; mi < 4; mi++)
#pragma unroll
                    for (int hh = 0; hh < 2; hh++)
                        mma_fp16(acc[mi][ni * 2 + hh], a[mi],
                                 bfr[hh], bfr[2 + hh]);
            }
        }
        __syncthreads();
        if (p + 3 < NC) issue(p + 3, cur);
    }

    // epilogue: warp writes 64x64
#pragma unroll
    for (int mi = 0; mi < 4; mi++) {
        int row0 = m0 + wm + mi * 16 + (lane >> 2);
#pragma unroll
        for (int nj = 0; nj < 8; nj++) {
            int col0 = n0 + wn + nj * 8 + (lane & 3) * 2;
            float b0 = bias ? __ldg(&bias[col0]) : 0.f;
            float b1 = bias ? __ldg(&bias[col0 + 1]) : 0.f;
            float* c = acc[mi][nj];
            *(float2*)&C[(size_t)row0 * N + col0] =
                make_float2(c[0] + b0, c[1] + b1);
            *(float2*)&C[(size_t)(row0 + 8) * N + col0] =
                make_float2(c[2] + b0, c[3] + b1);
        }
    }
}

// ---- RoPE Q+K from fused proj: [B,S,CW] slices -> [B,H,S,D] fp16 -----------
#define TOTQK (BATCH * (NQ + NKV) * SEQ * 64)

__global__ void ropeqk_kernel(const float* __restrict__ in,
                              __half* __restrict__ oq, __half* __restrict__ ok)
{
    int idx = blockIdx.x * blockDim.x + threadIdx.x;
    if (idx >= TOTQK) return;
    int per = idx;
    int d = per & 63;      per >>= 6;
    int s = per & (SEQ - 1); per >>= 11;
    int h = per & 31;
    int b = per >> 5;

    size_t ibase = ((size_t)b * SEQ + s) * CW + h * HD;
    float x1 = in[ibase + d];
    float x2 = in[ibase + d + 64];

    float cs = g_cs[(s << 6) + d];
    float sn = g_sn[(s << 6) + d];
    float v0 = x1 * cs - x2 * sn;
    float v1 = x2 * cs + x1 * sn;

    if (h < NQ) {
        size_t obase = (((size_t)b * NQ + h) * SEQ + s) * HD;
        oq[obase + d]      = __float2half(v0 * QSCALE);
        oq[obase + d + 64] = __float2half(v1 * QSCALE);
    } else {
        size_t obase = (((size_t)b * NKV + (h - NQ)) * SEQ + s) * HD;
        ok[obase + d]      = __float2half(v0);
        ok[obase + d + 64] = __float2half(v1);
    }
}

// ---- tiled V transpose: [B,S,CW] V-slice -> [B,Hkv,D,S] fp16 (coalesced) ---
__global__ void vtrans_tiled(const float* __restrict__ in, __half* __restrict__ out)
{
    __shared__ float tile[32][33];
    const int s0 = blockIdx.x * 32;
    const int d0 = blockIdx.y * 32;
    const int z  = blockIdx.z;           // b*NKV + h
    const int b  = z / NKV;
    const int h  = z % NKV;
    const int tx = threadIdx.x;          // 0..31
    const int ty = threadIdx.y;          // 0..7

    const float* src = in + ((size_t)b * SEQ + s0) * CW + VOFF + h * HD + d0;
#pragma unroll
    for (int g = 0; g < 4; g++) {
        int sl = ty + g * 8;
        tile[sl][tx] = src[(size_t)sl * CW + tx];
    }
    __syncthreads();

    __half* dst = out + ((size_t)z * HD + d0) * SEQ + s0;
#pragma unroll
    for (int g = 0; g < 4; g++) {
        int dl = ty + g * 8;
        dst[(size_t)dl * SEQ + tx] = __float2half(tile[tx][dl]);
    }
}

// ---------------- mma flash attention (fp16, 2-stage K/V) --------------------
#define AQW 64
#define KTS 64
#define KSTR 136
#define VSTR 72
#define ASTAGE_B (KTS * KSTR * 2 + HD * VSTR * 2)   // 35840 per stage
#define ASM_TOTAL (2 * ASTAGE_B)                    // 71680

__global__ __launch_bounds__(128) void attn_mma(
    const __half* __restrict__ Qg, const __half* __restrict__ Kg,
    const __half* __restrict__ Vg, const float* __restrict__ maskg,
    __half* __restrict__ Out)
{
    extern __shared__ __align__(16) char smraw[];
    const uint32_t smb = (uint32_t)__cvta_generic_to_shared(smraw);

    const int t    = threadIdx.x;
    const int lane = t & 31;
    const int w    = t >> 5;
    const int q0   = blockIdx.x * AQW;
    const int h    = blockIdx.y;
    const int b    = blockIdx.z;
    const int hkv  = h / NREP;
    const int wm   = w * 16;
    const int mnz  = g_mask_nz;

    const __half* q_b = Qg + (((size_t)(b * NQ + h) * SEQ) + q0) * HD;
    const __half* k_b = Kg + (size_t)(b * NKV + hkv) * SEQ * HD;
    const __half* v_b = Vg + (size_t)(b * NKV + hkv) * HD * SEQ;
    const float*  m_b = maskg + ((size_t)b * SEQ + q0) * SEQ;

    for (int c = t; c < 1024; c += 128) {
        int row = c >> 4, off = (c & 15) * 8;
        cp16(smb + (row * KSTR + off) * 2, q_b + (size_t)row * HD + off);
    }
    CP_COMMIT(); CP_WAIT0();
    __syncthreads();

    uint32_t qf[8][4];
    {
        const int arow = lane & 15;
#pragma unroll
        for (int ks = 0; ks < 8; ks++) {
            int acol = ks * 16 + (lane >> 4) * 8;
            ldsm4(qf[ks], smb + ((wm + arow) * KSTR + acol) * 2);
        }
    }
    __syncthreads();

    auto loadKV = [&](int kt, int buf) {
        int k0 = kt * KTS;
        uint32_t smk = smb + buf * ASTAGE_B;
        uint32_t smv = smk + KTS * KSTR * 2;
        for (int c = t; c < 1024; c += 128) {
            int row = c >> 4, off = (c & 15) * 8;
            cp16(smk + (row * KSTR + off) * 2, k_b + (size_t)(k0 + row) * HD + off);
        }
        for (int c = t; c < 1024; c += 128) {
            int row = c >> 3, off = (c & 7) * 8;
            cp16(smv + (row * VSTR + off) * 2, v_b + (size_t)row * SEQ + k0 + off);
        }
        CP_COMMIT();
    };

    float O[16][4];
#pragma unroll
    for (int j = 0; j < 16; j++)
#pragma unroll
        for (int e = 0; e < 4; e++) O[j][e] = 0.f;
    float mrow0 = -1e30f, mrow1 = -1e30f;
    float lrow0 = 0.f, lrow1 = 0.f;

    const int r0q = wm + (lane >> 2);
    const int cq  = (lane & 3) * 2;
    const float* mrow_a = m_b + (size_t)r0q * SEQ;
    const float* mrow_b = m_b + (size_t)(r0q + 8) * SEQ;

    loadKV(0, 0);

    const int NT = SEQ / KTS;
    for (int kt = 0; kt < NT; kt++) {
        const int cur = kt & 1;
        CP_WAIT0();
        __syncthreads();
        if (kt + 1 < NT) loadKV(kt + 1, cur ^ 1);

        const uint32_t smk = smb + cur * ASTAGE_B;
        const uint32_t smv = smk + KTS * KSTR * 2;
        const int k0 = kt * KTS;

        float sc[8][4];
#pragma unroll
        for (int j = 0; j < 8; j++)
#pragma unroll
            for (int e = 0; e < 4; e++) sc[j][e] = 0.f;

        const int arow = lane & 15;
#pragma unroll
        for (int ks = 0; ks < 8; ks++) {
            int acol = ks * 16 + (lane >> 4) * 8;
#pragma unroll
            for (int n = 0; n < 4; n++) {
                uint32_t bk[4];
                ldsm4(bk, smk + ((n * 16 + arow) * KSTR + acol) * 2);
#pragma unroll
                for (int hh = 0; hh < 2; hh++)
                    mma_fp16(sc[n * 2 + hh], qf[ks], bk[hh], bk[2 + hh]);
            }
        }

        if (mnz) {
#pragma unroll
            for (int j = 0; j < 8; j++) {
                float2 mk0 = __ldg((const float2*)(mrow_a + k0 + j * 8 + cq));
                float2 mk1 = __ldg((const float2*)(mrow_b + k0 + j * 8 + cq));
                sc[j][0] += mk0.x; sc[j][1] += mk0.y;
                sc[j][2] += mk1.x; sc[j][3] += mk1.y;
            }
        }
        float mx0 = -1e30f, mx1 = -1e30f;
#pragma unroll
        for (int j = 0; j < 8; j++) {
            mx0 = fmaxf(mx0, fmaxf(sc[j][0], sc[j][1]));
            mx1 = fmaxf(mx1, fmaxf(sc[j][2], sc[j][3]));
        }
        mx0 = qmax4(mx0); mx1 = qmax4(mx1);
        float mn0 = fmaxf(mrow0, mx0), mn1 = fmaxf(mrow1, mx1);
        float cr0 = __expf(mrow0 - mn0), cr1 = __expf(mrow1 - mn1);
        mrow0 = mn0; mrow1 = mn1;
        lrow0 *= cr0; lrow1 *= cr1;
#pragma unroll
        for (int j = 0; j < 16; j++) {
            O[j][0] *= cr0; O[j][1] *= cr0;
            O[j][2] *= cr1; O[j][3] *= cr1;
        }

        uint32_t ap[4][4];
#pragma unroll
        for (int j = 0; j < 8; j++) {
            float p0 = __expf(sc[j][0] - mn0);
            float p1 = __expf(sc[j][1] - mn0);
            float p2 = __expf(sc[j][2] - mn1);
            float p3 = __expf(sc[j][3] - mn1);
            lrow0 += p0 + p1; lrow1 += p2 + p3;
            int kk = j >> 1, hi = j & 1;
            __half2 ph01 = __floats2half2_rn(p0, p1);
            __half2 ph23 = __floats2half2_rn(p2, p3);
            ap[kk][hi * 2 + 0] = *(uint32_t*)&ph01;
            ap[kk][hi * 2 + 1] = *(uint32_t*)&ph23;
        }

#pragma unroll
        for (int kk = 0; kk < 4; kk++) {
            int acol = kk * 16 + (lane >> 4) * 8;
#pragma unroll
            for (int n = 0; n < 8; n++) {
                uint32_t bv[4];
                ldsm4(bv, smv + ((n * 16 + arow) * VSTR + acol) * 2);
#pragma unroll
                for (int hh = 0; hh < 2; hh++)
                    mma_fp16(O[n * 2 + hh], ap[kk], bv[hh], bv[2 + hh]);
            }
        }
    }

    float lt0 = qsum4(lrow0), lt1 = qsum4(lrow1);
    float inv0 = 1.f / lt0, inv1 = 1.f / lt1;

    const int r0 = q0 + r0q;
    __half* o_b = Out + ((size_t)b * SEQ) * (NQ * HD) + h * HD;
#pragma unroll
    for (int j = 0; j < 16; j++) {
        int col = j * 8 + cq;
        __half2 v0 = __floats2half2_rn(O[j][0] * inv0, O[j][1] * inv0);
        __half2 v1 = __floats2half2_rn(O[j][2] * inv1, O[j][3] * inv1);
        *(__half2*)&o_b[(size_t)r0 * (NQ * HD) + col]       = v0;
        *(__half2*)&o_b[(size_t)(r0 + 8) * (NQ * HD) + col] = v1;
    }
}

// ---------------- launcher ----------------------------------------------------
extern "C" void kernel_launch(void* const* d_in, const int* in_sizes, int n_in,
                              void* d_out, int out_size)
{
    const float* X    = (const float*)d_in[0];
    const float* mask = (const float*)d_in[1];
    const void*  pos  = (const void*)d_in[2];
    const float* wq   = (const float*)d_in[3];
    const float* bq   = (const float*)d_in[4];
    const float* wk   = (const float*)d_in[5];
    const float* bk   = (const float*)d_in[6];
    const float* wv   = (const float*)d_in[7];
    const float* bv   = (const float*)d_in[8];
    const float* wo   = (const float*)d_in[9];
    float*       out  = (float*)d_out;

    float *tmp, *bqkv;
    __half *a, *pwqkv, *pwo, *q, *k, *v;
    cudaGetSymbolAddress((void**)&tmp,   g_tmp);
    cudaGetSymbolAddress((void**)&a,     g_a);
    cudaGetSymbolAddress((void**)&pwqkv, g_wqkv);
    cudaGetSymbolAddress((void**)&bqkv,  g_bqkv);
    cudaGetSymbolAddress((void**)&pwo,   g_wo);
    cudaGetSymbolAddress((void**)&q,     g_q);
    cudaGetSymbolAddress((void**)&k,     g_k);
    cudaGetSymbolAddress((void**)&v,     g_v);

    cudaFuncSetAttribute(attn_mma, cudaFuncAttributeMaxDynamicSharedMemorySize,
                         ASM_TOTAL);
    cudaFuncSetAttribute(gemm_fp16, cudaFuncAttributeMaxDynamicSharedMemorySize,
                         GSM_TOTAL);

    const int M = BATCH * SEQ;   // 4096

    // prep: quants + bias concat + rope table + mask scan (one launch)
    {
        const int nq4 = (NQ * HD * HIDDEN) / 4;
        const int nk4 = (NKV * HD * HIDDEN) / 4;
        const int no4 = (HIDDEN * HIDDEN) / 4;
        const int nx4 = (M * HIDDEN) / 4;
        const int nm4 = (BATCH * SEQ * SEQ) / 4;
        int total = nq4 + 2 * nk4 + no4 + nx4 + CW / 4 + SEQ * 64 + nm4;
        prep_kernel<<<(total + 255) / 256, 256>>>(wq, wk, wv, wo, X, bq, bk, bv,
                                                  pos, (const float4*)mask,
                                                  pwqkv, pwo, a, bqkv,
                                                  nq4, nk4, no4, nx4, nm4);
    }
    // fused QKV projection
    {
        dim3 grid(CW / 256, M / 128);
        gemm_fp16<<<grid, 256, GSM_TOTAL>>>(a, pwqkv, bqkv, tmp, M, CW, HIDDEN);
    }
    // RoPE Q+K, tiled V transpose
    {
        ropeqk_kernel<<<(TOTQK + 255) / 256, 256>>>(tmp, q, k);
        dim3 vg(SEQ / 32, HD / 32, BATCH * NKV);
        vtrans_tiled<<<vg, dim3(32, 8)>>>(tmp, v);
    }
    // attention -> fp16 context written into g_a (X no longer needed)
    {
        dim3 grid(SEQ / AQW, NQ, BATCH);
        attn_mma<<<grid, 128, ASM_TOTAL>>>(q, k, v, mask, a);
    }
    // output projection (no bias)
    {
        dim3 grid(HIDDEN / 256, M / 128);
        gemm_fp16<<<grid, 256, GSM_TOTAL>>>(a, pwo, nullptr, out, M, HIDDEN, HIDDEN);
    }
}